// round 1
// baseline (speedup 1.0000x reference)
#include <cuda_runtime.h>
#include <math.h>

// Problem constants
#define NP 4096   // persons
#define NI 256    // items
#define NH 64     // hidden
#define NA 32     // ability dims

// Lookup table for h2(x) = elu(elu(elu(x*w1+b1)@w2+b2))  (x scalar in [0,1))
#define NBINS 512
#define TROWS (NBINS + 1)

// Output layout (flattened concatenation of reference return tuple, fp32):
// response_mu [P*I] | ability_mu [P*A] | ability_logvar [P*A] | item_mu [I] | item_logvar [I]
#define O_RESP 0
#define O_AMU  (NP * NI)                 // 1048576
#define O_ALV  (O_AMU + NP * NA)         // 1179648
#define O_IMU  (O_ALV + NP * NA)         // 1310720
#define O_ILV  (O_IMU + NI)              // 1310976

__device__ float g_table[TROWS * NH];

__device__ __forceinline__ float elu_f(float x) {
    return x > 0.0f ? x : expm1f(x);
}

// ---------------------------------------------------------------------------
// Kernel 1: build the h2(x) lookup table once per launch (trivial cost).
// ---------------------------------------------------------------------------
__global__ void build_table_kernel(const float* __restrict__ w1,
                                   const float* __restrict__ b1,
                                   const float* __restrict__ w2,
                                   const float* __restrict__ b2) {
    int idx = blockIdx.x * blockDim.x + threadIdx.x;
    if (idx >= TROWS * NH) return;
    int row = idx >> 6;   // bin index 0..512
    int j   = idx & 63;   // hidden dim
    float x = (float)row * (1.0f / (float)NBINS);
    float z = b2[j];
#pragma unroll 8
    for (int k = 0; k < NH; k++) {
        float h1 = elu_f(fmaf(w1[k], x, b1[k]));
        z = fmaf(h1, w2[k * NH + j], z);
    }
    g_table[idx] = elu_f(z);
}

// ---------------------------------------------------------------------------
// Kernel 2: persistent main kernel. One CTA per SM, loops over persons.
// ---------------------------------------------------------------------------
struct SM {
    float table[TROWS * NH];   // 131328 B
    float w3[NH * NH];         // 16384 B
    float w4[NH * NH];         // 16384 B
    float fs[NI];              // interp fraction per item
    int   offs[NI];            // table row offset (bin*64) or -1 if masked out
    float ifeat[NI];           // item_mu + eps_item * exp(0.5*item_logvar)
    float red[8 * NH];         // cross-group reduction buffer
    float redc[8];             // mask counts per group
    float hm[NH];              // hid_mean
    float u[NH];               // elu(hid_mean@w3+b3)
    float ovec[NH];            // final layer output (mu | logvar)
    float asum;                // sum over ability dims
};

__global__ __launch_bounds__(512, 1)
void vibo_main_kernel(const float* __restrict__ response,
                      const int*   __restrict__ mask,
                      const int*   __restrict__ item_index,
                      const float* __restrict__ eps_ability,
                      const float* __restrict__ eps_item,
                      const float* __restrict__ w3,
                      const float* __restrict__ b3,
                      const float* __restrict__ w4,
                      const float* __restrict__ b4,
                      const float* __restrict__ mu_table,
                      const float* __restrict__ logvar_table,
                      float* __restrict__ out) {
    extern __shared__ char smraw[];
    SM* s = (SM*)smraw;
    int tid = threadIdx.x;

    // ---- CTA prologue: stage table + weights + item features in smem ----
    for (int i = tid; i < TROWS * NH; i += 512) s->table[i] = g_table[i];
    for (int i = tid; i < NH * NH; i += 512) {
        s->w3[i] = w3[i];
        s->w4[i] = w4[i];
    }
    if (tid < NI) {
        int idx = item_index[tid];
        float imu = mu_table[idx];
        float ilv = logvar_table[idx];
        s->ifeat[tid] = fmaf(eps_item[tid], expf(0.5f * ilv), imu);
        if (blockIdx.x == 0) {
            out[O_IMU + tid] = imu;
            out[O_ILV + tid] = ilv;
        }
    }
    __syncthreads();

    const int d = tid & 63;   // hidden dim handled by this thread
    const int g = tid >> 6;   // item-group 0..7

    for (int p = blockIdx.x; p < NP; p += gridDim.x) {
        // ---- stage this person's items: bin, fraction, mask ----
        if (tid < NI) {
            float x = response[p * NI + tid];
            int   m = mask[p * NI + tid];
            float v = x * (float)NBINS;
            int b = (int)v;
            if (b > NBINS - 1) b = NBINS - 1;
            if (b < 0) b = 0;
            s->fs[tid]   = v - (float)b;
            s->offs[tid] = m ? (b << 6) : -1;
        }
        __syncthreads();

        // ---- masked accumulate of lerped h2 rows ----
        float acc = 0.0f, cf = 0.0f;
#pragma unroll 4
        for (int i = g; i < NI; i += 8) {
            int off = s->offs[i];            // warp-uniform (all lanes same item)
            if (off >= 0) {
                float f  = s->fs[i];
                float t0 = s->table[off + d];
                float t1 = s->table[off + 64 + d];
                acc = fmaf(f, t1 - t0, acc + t0);
                cf += 1.0f;
            }
        }
        s->red[(g << 6) + d] = acc;
        if (d == 0) s->redc[g] = cf;
        __syncthreads();

        // ---- reduce 8 groups -> hid_mean ----
        if (tid < NH) {
            float ssum = 0.0f;
#pragma unroll
            for (int q = 0; q < 8; q++) ssum += s->red[(q << 6) + tid];
            float cnt = 0.0f;
#pragma unroll
            for (int q = 0; q < 8; q++) cnt += s->redc[q];
            s->hm[tid] = ssum / fmaxf(cnt, 1.0f);
        }
        __syncthreads();

        // ---- layer 3: u = elu(hm @ w3 + b3); 256 threads, 4-way k-split ----
        if (tid < 256) {
            int j = tid & 63, q = tid >> 6;
            float part = (q == 0) ? b3[j] : 0.0f;
            int k0 = q * 16;
#pragma unroll
            for (int k = 0; k < 16; k++)
                part = fmaf(s->hm[k0 + k], s->w3[(k0 + k) * NH + j], part);
            s->red[(q << 6) + j] = part;
        }
        __syncthreads();
        if (tid < NH) {
            float z = s->red[tid] + s->red[64 + tid] + s->red[128 + tid] + s->red[192 + tid];
            s->u[tid] = elu_f(z);
        }
        __syncthreads();

        // ---- layer 4: out = u @ w4 + b4 ----
        if (tid < 256) {
            int j = tid & 63, q = tid >> 6;
            float part = (q == 0) ? b4[j] : 0.0f;
            int k0 = q * 16;
#pragma unroll
            for (int k = 0; k < 16; k++)
                part = fmaf(s->u[k0 + k], s->w4[(k0 + k) * NH + j], part);
            s->red[(q << 6) + j] = part;
        }
        __syncthreads();
        if (tid < NH) {
            float o = s->red[tid] + s->red[64 + tid] + s->red[128 + tid] + s->red[192 + tid];
            s->ovec[tid] = o;
            if (tid < NA) out[O_AMU + p * NA + tid] = o;
            else          out[O_ALV + p * NA + (tid - NA)] = o;
        }
        __syncthreads();

        // ---- ability sum = sum_a (mu + eps * exp(0.5*logvar)) ----
        if (tid < NA) {
            float term = fmaf(eps_ability[p * NA + tid],
                              expf(0.5f * s->ovec[NA + tid]),
                              s->ovec[tid]);
#pragma unroll
            for (int w = 16; w > 0; w >>= 1)
                term += __shfl_xor_sync(0xffffffffu, term, w);
            if (tid == 0) s->asum = term;
        }
        __syncthreads();

        // ---- response_mu = sigmoid(asum + item_feat) ----
        if (tid < NI) {
            float z = s->asum + s->ifeat[tid];
            out[O_RESP + p * NI + tid] = 1.0f / (1.0f + expf(-z));
        }
        __syncthreads();   // protect fs/offs/red for next person
    }
}

// ---------------------------------------------------------------------------
// Launch
// ---------------------------------------------------------------------------
extern "C" void kernel_launch(void* const* d_in, const int* in_sizes, int n_in,
                              void* d_out, int out_size) {
    const float* response     = (const float*)d_in[0];
    const int*   mask         = (const int*)  d_in[1];
    const int*   item_index   = (const int*)  d_in[2];
    const float* eps_ability  = (const float*)d_in[3];
    const float* eps_item     = (const float*)d_in[4];
    const float* w1           = (const float*)d_in[5];
    const float* b1           = (const float*)d_in[6];
    const float* w2           = (const float*)d_in[7];
    const float* b2           = (const float*)d_in[8];
    const float* w3           = (const float*)d_in[9];
    const float* b3           = (const float*)d_in[10];
    const float* w4           = (const float*)d_in[11];
    const float* b4           = (const float*)d_in[12];
    const float* mu_table     = (const float*)d_in[13];
    const float* logvar_table = (const float*)d_in[14];
    float* out = (float*)d_out;

    cudaFuncSetAttribute(vibo_main_kernel,
                         cudaFuncAttributeMaxDynamicSharedMemorySize,
                         (int)sizeof(SM));

    int nblocks = (TROWS * NH + 255) / 256;
    build_table_kernel<<<nblocks, 256>>>(w1, b1, w2, b2);

    int sms = 148;
    cudaDeviceGetAttribute(&sms, cudaDevAttrMultiProcessorCount, 0);
    vibo_main_kernel<<<sms, 512, sizeof(SM)>>>(response, mask, item_index,
                                               eps_ability, eps_item,
                                               w3, b3, w4, b4,
                                               mu_table, logvar_table, out);
}

// round 2
// speedup vs baseline: 2.6846x; 2.6846x over previous
#include <cuda_runtime.h>
#include <math.h>

// Problem constants
#define NP 4096
#define NI 256
#define NH 64
#define NA 32

// h2(x) lookup table
#define NBINS 256
#define TROWS (NBINS + 1)

// Output layout (flattened tuple, fp32):
// response_mu [P*I] | ability_mu [P*A] | ability_logvar [P*A] | item_mu [I] | item_logvar [I]
#define O_AMU  (NP * NI)
#define O_ALV  (O_AMU + NP * NA)
#define O_IMU  (O_ALV + NP * NA)
#define O_ILV  (O_IMU + NI)

__device__ float g_table[TROWS * NH];

__device__ __forceinline__ float elu_f(float x) {
    return x > 0.0f ? x : expm1f(x);
}

// ---------------------------------------------------------------------------
// Kernel 1: build h2(x) table. One block per bin row; h1 shared across j.
// ---------------------------------------------------------------------------
__global__ void build_table_kernel(const float* __restrict__ w1,
                                   const float* __restrict__ b1,
                                   const float* __restrict__ w2,
                                   const float* __restrict__ b2) {
    __shared__ float h1[NH];
    int row = blockIdx.x;
    int j = threadIdx.x;
    float x = (float)row * (1.0f / (float)NBINS);
    h1[j] = elu_f(fmaf(w1[j], x, b1[j]));
    __syncthreads();
    float z = b2[j];
#pragma unroll 8
    for (int k = 0; k < NH; k++)
        z = fmaf(h1[k], w2[k * NH + j], z);
    g_table[row * NH + j] = elu_f(z);
}

// ---------------------------------------------------------------------------
// Kernel 2: one WARP per person. 1024 threads = 32 warps/CTA; no block syncs
// after the staging prologue. Each thread owns 2 hidden dims (float2).
// ---------------------------------------------------------------------------
struct SM {
    float  table[TROWS * NH];   // 65792 B
    float  w3[NH * NH];         // 16384 B
    float  w4[NH * NH];         // 16384 B
    float  ifeat[NI];           // 1024 B
    float2 cmp[32][NI];         // 65536 B  (per-warp compacted {f, off})
    float  buf[32][NH];         // 8192 B   (per-warp hm/u exchange)
};                              // total 173312 B

__global__ __launch_bounds__(1024, 1)
void vibo_main_kernel(const float* __restrict__ response,
                      const int*   __restrict__ mask,
                      const int*   __restrict__ item_index,
                      const float* __restrict__ eps_ability,
                      const float* __restrict__ eps_item,
                      const float* __restrict__ w3,
                      const float* __restrict__ b3,
                      const float* __restrict__ w4,
                      const float* __restrict__ b4,
                      const float* __restrict__ mu_table,
                      const float* __restrict__ logvar_table,
                      float* __restrict__ out) {
    extern __shared__ char smraw[];
    SM* s = (SM*)smraw;
    int tid = threadIdx.x;

    // ---- stage table + weights + item features ----
    for (int i = tid; i < TROWS * NH; i += 1024) s->table[i] = g_table[i];
    for (int i = tid; i < NH * NH; i += 1024) {
        s->w3[i] = w3[i];
        s->w4[i] = w4[i];
    }
    if (tid < NI) {
        int idx = item_index[tid];
        float imu = mu_table[idx];
        float ilv = logvar_table[idx];
        s->ifeat[tid] = fmaf(eps_item[tid], __expf(0.5f * ilv), imu);
        if (blockIdx.x == 0) {
            out[O_IMU + tid] = imu;
            out[O_ILV + tid] = ilv;
        }
    }
    __syncthreads();   // the only block-wide sync

    const int wid  = tid >> 5;
    const int lane = tid & 31;
    const int p = blockIdx.x * 32 + wid;
    if (p >= NP) return;

    // ---- load + compact this person's masked items (8 items per lane) ----
    const float4* rp = (const float4*)(response + p * NI);
    const int4*   mp = (const int4*)(mask + p * NI);
    float4 r0 = rp[lane * 2], r1 = rp[lane * 2 + 1];
    int4   m0 = mp[lane * 2], m1 = mp[lane * 2 + 1];
    float rv[8] = {r0.x, r0.y, r0.z, r0.w, r1.x, r1.y, r1.z, r1.w};
    int   mv[8] = {m0.x, m0.y, m0.z, m0.w, m1.x, m1.y, m1.z, m1.w};

    int cnt = 0;
#pragma unroll
    for (int j = 0; j < 8; j++) cnt += (mv[j] != 0);

    // inclusive warp scan -> exclusive offset
    int off = cnt;
#pragma unroll
    for (int d = 1; d < 32; d <<= 1) {
        int t = __shfl_up_sync(0xffffffffu, off, d);
        if (lane >= d) off += t;
    }
    int total = __shfl_sync(0xffffffffu, off, 31);
    off -= cnt;

    float2* cmp = s->cmp[wid];
    int pos = off;
#pragma unroll
    for (int j = 0; j < 8; j++) {
        if (mv[j]) {
            float v = rv[j] * (float)NBINS;
            int b = (int)v;
            if (b > NBINS - 1) b = NBINS - 1;
            if (b < 0) b = 0;
            cmp[pos++] = make_float2(v - (float)b, __int_as_float(b << 6));
        }
    }
    __syncwarp();

    // ---- main lerp-accumulate over compacted items; 2 dims per thread ----
    const int d0 = lane * 2;
    float accx = 0.0f, accy = 0.0f;
#pragma unroll 4
    for (int i = 0; i < total; i++) {
        float2 e = cmp[i];
        int ro = __float_as_int(e.y);
        float f = e.x, omf = 1.0f - f;
        float2 t0 = *(const float2*)&s->table[ro + d0];
        float2 t1 = *(const float2*)&s->table[ro + NH + d0];
        accx = fmaf(omf, t0.x, accx);
        accy = fmaf(omf, t0.y, accy);
        accx = fmaf(f, t1.x, accx);
        accy = fmaf(f, t1.y, accy);
    }
    float inv = 1.0f / fmaxf((float)total, 1.0f);
    float* buf = s->buf[wid];
    buf[d0]     = accx * inv;
    buf[d0 + 1] = accy * inv;
    __syncwarp();

    // ---- layer 3: u = elu(hm @ w3 + b3) ----
    float z0 = b3[d0], z1 = b3[d0 + 1];
#pragma unroll 4
    for (int k = 0; k < NH; k++) {
        float hk = buf[k];
        float2 w = *(const float2*)&s->w3[k * NH + d0];
        z0 = fmaf(hk, w.x, z0);
        z1 = fmaf(hk, w.y, z1);
    }
    float u0 = elu_f(z0), u1 = elu_f(z1);
    __syncwarp();
    buf[d0]     = u0;
    buf[d0 + 1] = u1;
    __syncwarp();

    // ---- layer 4: o = u @ w4 + b4 ----
    float o0 = b4[d0], o1 = b4[d0 + 1];
#pragma unroll 4
    for (int k = 0; k < NH; k++) {
        float uk = buf[k];
        float2 w = *(const float2*)&s->w4[k * NH + d0];
        o0 = fmaf(uk, w.x, o0);
        o1 = fmaf(uk, w.y, o1);
    }

    // ---- write ability mu/logvar (lanes 0-15: mu dims, 16-31: logvar) ----
    float2 ov = make_float2(o0, o1);
    if (lane < 16) *(float2*)&out[O_AMU + p * NA + d0] = ov;
    else           *(float2*)&out[O_ALV + p * NA + (d0 - NA)] = ov;

    // ---- asum = sum_a mu_a + eps_a * exp(0.5*logvar_a) ----
    float lv0 = __shfl_down_sync(0xffffffffu, o0, 16);
    float lv1 = __shfl_down_sync(0xffffffffu, o1, 16);
    float term = 0.0f;
    if (lane < 16) {
        float2 eps = *(const float2*)&eps_ability[p * NA + d0];
        term = o0 + eps.x * __expf(0.5f * lv0)
             + o1 + eps.y * __expf(0.5f * lv1);
    }
#pragma unroll
    for (int w = 16; w > 0; w >>= 1)
        term += __shfl_xor_sync(0xffffffffu, term, w);
    float asum = term;

    // ---- response_mu = sigmoid(asum + item_feat) ----
    float* orow = out + p * NI;
#pragma unroll
    for (int j = 0; j < 8; j++) {
        int i = j * 32 + lane;
        float zz = asum + s->ifeat[i];
        orow[i] = __fdividef(1.0f, 1.0f + __expf(-zz));
    }
}

// ---------------------------------------------------------------------------
extern "C" void kernel_launch(void* const* d_in, const int* in_sizes, int n_in,
                              void* d_out, int out_size) {
    const float* response     = (const float*)d_in[0];
    const int*   mask         = (const int*)  d_in[1];
    const int*   item_index   = (const int*)  d_in[2];
    const float* eps_ability  = (const float*)d_in[3];
    const float* eps_item     = (const float*)d_in[4];
    const float* w1           = (const float*)d_in[5];
    const float* b1           = (const float*)d_in[6];
    const float* w2           = (const float*)d_in[7];
    const float* b2           = (const float*)d_in[8];
    const float* w3           = (const float*)d_in[9];
    const float* b3           = (const float*)d_in[10];
    const float* w4           = (const float*)d_in[11];
    const float* b4           = (const float*)d_in[12];
    const float* mu_table     = (const float*)d_in[13];
    const float* logvar_table = (const float*)d_in[14];
    float* out = (float*)d_out;

    cudaFuncSetAttribute(vibo_main_kernel,
                         cudaFuncAttributeMaxDynamicSharedMemorySize,
                         (int)sizeof(SM));

    build_table_kernel<<<TROWS, NH>>>(w1, b1, w2, b2);

    int sms = 148;
    cudaDeviceGetAttribute(&sms, cudaDevAttrMultiProcessorCount, 0);
    int grid = sms;
    if (grid * 32 < NP) grid = (NP + 31) / 32;
    vibo_main_kernel<<<grid, 1024, sizeof(SM)>>>(response, mask, item_index,
                                                 eps_ability, eps_item,
                                                 w3, b3, w4, b4,
                                                 mu_table, logvar_table, out);
}

// round 3
// speedup vs baseline: 3.3704x; 1.2554x over previous
#include <cuda_runtime.h>
#include <math.h>

#define NP 4096
#define NI 256
#define NH 64
#define NA 32

#define NBINS 1024
#define TROWS (NBINS + 1)

// Output layout (flattened tuple, fp32):
// response_mu [P*I] | ability_mu [P*A] | ability_logvar [P*A] | item_mu [I] | item_logvar [I]
#define O_AMU  (NP * NI)
#define O_ALV  (O_AMU + NP * NA)
#define O_IMU  (O_ALV + NP * NA)
#define O_ILV  (O_IMU + NI)

// bf16x2-packed h2 table: word w of row r packs dims (2w, 2w+1)
__device__ unsigned int g_table[TROWS * 32];

__device__ __forceinline__ float elu_f(float x) {
    return x > 0.0f ? x : expm1f(x);
}

// ---------------------------------------------------------------------------
// Kernel 1: build h2(x) table, bf16x2-packed. One block (64 thr) per bin row.
// ---------------------------------------------------------------------------
__global__ void build_table_kernel(const float* __restrict__ w1,
                                   const float* __restrict__ b1,
                                   const float* __restrict__ w2,
                                   const float* __restrict__ b2) {
    __shared__ float h1[NH];
    int row = blockIdx.x;
    int j = threadIdx.x;            // 0..63, dim
    float x = (float)row * (1.0f / (float)NBINS);
    h1[j] = elu_f(fmaf(w1[j], x, b1[j]));
    __syncthreads();
    float z = b2[j];
#pragma unroll 8
    for (int k = 0; k < NH; k++)
        z = fmaf(h1[k], w2[k * NH + j], z);
    z = elu_f(z);
    // pack pairs: even lane takes partner's (odd dim) value as high half
    float zo = __shfl_xor_sync(0xffffffffu, z, 1);
    if ((j & 1) == 0) {
        unsigned int u;
        asm("cvt.rn.bf16x2.f32 %0, %1, %2;" : "=r"(u) : "f"(zo), "f"(z));
        g_table[row * 32 + (j >> 1)] = u;
    }
}

// ---------------------------------------------------------------------------
// Kernel 2: one warp per person, packed f32x2 math, nearest-neighbor table.
// ---------------------------------------------------------------------------
struct SM {
    unsigned int   table[TROWS * 32];   // 131200 B (bf16x2)
    float          w3[NH * NH];         // 16384 B
    float          w4[NH * NH];         // 16384 B
    float          ifeat[NI];           // 1024 B
    unsigned short cmp[32][NI];         // 16384 B (per-warp compacted word-offsets)
};                                      // ~181 KB

__global__ __launch_bounds__(1024, 1)
void vibo_main_kernel(const float* __restrict__ response,
                      const int*   __restrict__ mask,
                      const int*   __restrict__ item_index,
                      const float* __restrict__ eps_ability,
                      const float* __restrict__ eps_item,
                      const float* __restrict__ w3,
                      const float* __restrict__ b3,
                      const float* __restrict__ w4,
                      const float* __restrict__ b4,
                      const float* __restrict__ mu_table,
                      const float* __restrict__ logvar_table,
                      float* __restrict__ out) {
    extern __shared__ char smraw[];
    SM* s = (SM*)smraw;
    const int tid = threadIdx.x;
    const int nthr = blockDim.x;

    // ---- stage table + weights + item features ----
    for (int i = tid; i < TROWS * 32; i += nthr) s->table[i] = g_table[i];
    for (int i = tid; i < NH * NH; i += nthr) {
        s->w3[i] = w3[i];
        s->w4[i] = w4[i];
    }
    if (tid < NI) {
        int idx = item_index[tid];
        float imu = mu_table[idx];
        float ilv = logvar_table[idx];
        s->ifeat[tid] = fmaf(eps_item[tid], __expf(0.5f * ilv), imu);
        if (blockIdx.x == 0) {
            out[O_IMU + tid] = imu;
            out[O_ILV + tid] = ilv;
        }
    }
    __syncthreads();

    const int wid  = tid >> 5;
    const int lane = tid & 31;
    const int wpc  = nthr >> 5;               // warps (persons) per CTA
    const int p = blockIdx.x * wpc + wid;
    if (p >= NP) return;

    // ---- load + compact this person's masked items (8 per lane) ----
    const float4* rp = (const float4*)(response + p * NI);
    const int4*   mp = (const int4*)(mask + p * NI);
    float4 r0 = rp[lane * 2], r1 = rp[lane * 2 + 1];
    int4   m0 = mp[lane * 2], m1 = mp[lane * 2 + 1];
    float rv[8] = {r0.x, r0.y, r0.z, r0.w, r1.x, r1.y, r1.z, r1.w};
    int   mv[8] = {m0.x, m0.y, m0.z, m0.w, m1.x, m1.y, m1.z, m1.w};

    int cnt = 0;
#pragma unroll
    for (int j = 0; j < 8; j++) cnt += (mv[j] != 0);

    int off = cnt;
#pragma unroll
    for (int d = 1; d < 32; d <<= 1) {
        int t = __shfl_up_sync(0xffffffffu, off, d);
        if (lane >= d) off += t;
    }
    int total = __shfl_sync(0xffffffffu, off, 31);
    off -= cnt;

    unsigned short* cmp = s->cmp[wid];
    int pos = off;
#pragma unroll
    for (int j = 0; j < 8; j++) {
        if (mv[j]) {
            int b = __float2int_rn(rv[j] * (float)NBINS);
            if (b < 0) b = 0;
            if (b > NBINS) b = NBINS;
            cmp[pos++] = (unsigned short)(b << 5);   // word-offset of row
        }
    }
    __syncwarp();

    // ---- nearest-neighbor accumulate: 1 LDS.32 + unpack + add.f32x2 per item
    const unsigned int* cw = (const unsigned int*)cmp;
    const unsigned int* tab = s->table + lane;
    unsigned long long acc = 0ull;   // packed {f32 dim 2l, f32 dim 2l+1}
    int nw = total >> 1;
#pragma unroll 4
    for (int i = 0; i < nw; i++) {
        unsigned int w = cw[i];                  // broadcast: 2 items
        unsigned int u0 = tab[w & 0xffffu];
        unsigned int u1 = tab[w >> 16];
        asm("{\n\t"
            ".reg .b32 lo, hi;\n\t"
            ".reg .b64 t;\n\t"
            "shl.b32 lo, %1, 16;\n\t"
            "and.b32 hi, %1, 0xffff0000;\n\t"
            "mov.b64 t, {lo, hi};\n\t"
            "add.rn.f32x2 %0, %0, t;\n\t"
            "shl.b32 lo, %2, 16;\n\t"
            "and.b32 hi, %2, 0xffff0000;\n\t"
            "mov.b64 t, {lo, hi};\n\t"
            "add.rn.f32x2 %0, %0, t;\n\t"
            "}" : "+l"(acc) : "r"(u0), "r"(u1));
    }
    if (total & 1) {
        unsigned int w = cw[nw];
        unsigned int u0 = tab[w & 0xffffu];
        asm("{\n\t"
            ".reg .b32 lo, hi;\n\t"
            ".reg .b64 t;\n\t"
            "shl.b32 lo, %1, 16;\n\t"
            "and.b32 hi, %1, 0xffff0000;\n\t"
            "mov.b64 t, {lo, hi};\n\t"
            "add.rn.f32x2 %0, %0, t;\n\t"
            "}" : "+l"(acc) : "r"(u0));
    }

    float hx, hy;
    asm("mov.b64 {%0, %1}, %2;" : "=f"(hx), "=f"(hy) : "l"(acc));
    float inv = 1.0f / fmaxf((float)total, 1.0f);
    float hm_lo = hx * inv;           // dim 2*lane
    float hm_hi = hy * inv;           // dim 2*lane + 1

    const int d0 = lane * 2;

    // ---- layer 3: u = elu(hm @ w3 + b3), shfl-broadcast h, FMA2 ----
    const float2* b3p = (const float2*)(b3 + d0);
    float2 bb = *b3p;
    unsigned long long z;
    asm("mov.b64 %0, {%1, %2};" : "=l"(z) : "f"(bb.x), "f"(bb.y));
#pragma unroll
    for (int k = 0; k < NH; k++) {
        float hk = __shfl_sync(0xffffffffu, (k & 1) ? hm_hi : hm_lo, k >> 1);
        unsigned long long wv = *(const unsigned long long*)&s->w3[k * NH + d0];
        asm("{\n\t"
            ".reg .b64 hh;\n\t"
            "mov.b64 hh, {%1, %1};\n\t"
            "fma.rn.f32x2 %0, hh, %2, %0;\n\t"
            "}" : "+l"(z) : "f"(hk), "l"(wv));
    }
    float z0, z1;
    asm("mov.b64 {%0, %1}, %2;" : "=f"(z0), "=f"(z1) : "l"(z));
    float u_lo = elu_f(z0), u_hi = elu_f(z1);

    // ---- layer 4: o = u @ w4 + b4 ----
    const float2* b4p = (const float2*)(b4 + d0);
    float2 bb4 = *b4p;
    asm("mov.b64 %0, {%1, %2};" : "=l"(z) : "f"(bb4.x), "f"(bb4.y));
#pragma unroll
    for (int k = 0; k < NH; k++) {
        float uk = __shfl_sync(0xffffffffu, (k & 1) ? u_hi : u_lo, k >> 1);
        unsigned long long wv = *(const unsigned long long*)&s->w4[k * NH + d0];
        asm("{\n\t"
            ".reg .b64 hh;\n\t"
            "mov.b64 hh, {%1, %1};\n\t"
            "fma.rn.f32x2 %0, hh, %2, %0;\n\t"
            "}" : "+l"(z) : "f"(uk), "l"(wv));
    }
    float o0, o1;
    asm("mov.b64 {%0, %1}, %2;" : "=f"(o0), "=f"(o1) : "l"(z));

    // ---- write ability mu/logvar (lanes 0-15 mu, 16-31 logvar) ----
    float2 ov = make_float2(o0, o1);
    if (lane < 16) *(float2*)&out[O_AMU + p * NA + d0] = ov;
    else           *(float2*)&out[O_ALV + p * NA + (d0 - NA)] = ov;

    // ---- asum ----
    float lv0 = __shfl_down_sync(0xffffffffu, o0, 16);
    float lv1 = __shfl_down_sync(0xffffffffu, o1, 16);
    float term = 0.0f;
    if (lane < 16) {
        float2 eps = *(const float2*)&eps_ability[p * NA + d0];
        term = o0 + eps.x * __expf(0.5f * lv0)
             + o1 + eps.y * __expf(0.5f * lv1);
    }
#pragma unroll
    for (int w = 16; w > 0; w >>= 1)
        term += __shfl_xor_sync(0xffffffffu, term, w);
    float asum = term;

    // ---- response_mu = sigmoid(asum + ifeat) ----
    float* orow = out + p * NI;
#pragma unroll
    for (int j = 0; j < 8; j++) {
        int i = j * 32 + lane;
        float zz = asum + s->ifeat[i];
        orow[i] = __fdividef(1.0f, 1.0f + __expf(-zz));
    }
}

// ---------------------------------------------------------------------------
extern "C" void kernel_launch(void* const* d_in, const int* in_sizes, int n_in,
                              void* d_out, int out_size) {
    const float* response     = (const float*)d_in[0];
    const int*   mask         = (const int*)  d_in[1];
    const int*   item_index   = (const int*)  d_in[2];
    const float* eps_ability  = (const float*)d_in[3];
    const float* eps_item     = (const float*)d_in[4];
    const float* w1           = (const float*)d_in[5];
    const float* b1           = (const float*)d_in[6];
    const float* w2           = (const float*)d_in[7];
    const float* b2           = (const float*)d_in[8];
    const float* w3           = (const float*)d_in[9];
    const float* b3           = (const float*)d_in[10];
    const float* w4           = (const float*)d_in[11];
    const float* b4           = (const float*)d_in[12];
    const float* mu_table     = (const float*)d_in[13];
    const float* logvar_table = (const float*)d_in[14];
    float* out = (float*)d_out;

    cudaFuncSetAttribute(vibo_main_kernel,
                         cudaFuncAttributeMaxDynamicSharedMemorySize,
                         (int)sizeof(SM));

    build_table_kernel<<<TROWS, NH>>>(w1, b1, w2, b2);

    int sms = 148;
    cudaDeviceGetAttribute(&sms, cudaDevAttrMultiProcessorCount, 0);
    int wpc = (NP + sms - 1) / sms;          // persons (warps) per CTA
    if (wpc > 32) wpc = 32;
    if (wpc < 1)  wpc = 1;
    int grid = (NP + wpc - 1) / wpc;
    vibo_main_kernel<<<grid, wpc * 32, sizeof(SM)>>>(response, mask, item_index,
                                                     eps_ability, eps_item,
                                                     w3, b3, w4, b4,
                                                     mu_table, logvar_table, out);
}

// round 4
// speedup vs baseline: 4.0290x; 1.1954x over previous
#include <cuda_runtime.h>
#include <math.h>

#define NP 4096
#define NI 256
#define NH 64
#define NA 32

#define NBINS 512
#define TROWS (NBINS + 1)     // rows 0..512
#define PADROW TROWS          // row 513 = zeros (loop padding)
#define TROWS_ALL (TROWS + 1) // 514 rows in smem

// Output layout (flattened tuple, fp32):
// response_mu [P*I] | ability_mu [P*A] | ability_logvar [P*A] | item_mu [I] | item_logvar [I]
#define O_AMU  (NP * NI)
#define O_ALV  (O_AMU + NP * NA)
#define O_IMU  (O_ALV + NP * NA)
#define O_ILV  (O_IMU + NI)

__device__ float g_table[TROWS * NH];

__device__ __forceinline__ float elu_f(float x) {
    return x > 0.0f ? x : expm1f(x);
}

__device__ __forceinline__ void add2(unsigned long long& acc, const float* p) {
    asm("add.rn.f32x2 %0, %0, %1;"
        : "+l"(acc) : "l"(*(const unsigned long long*)p));
}

// ---------------------------------------------------------------------------
// Kernel 1: build fp32 h2(x) table. One 64-thread block per bin row.
// ---------------------------------------------------------------------------
__global__ void build_table_kernel(const float* __restrict__ w1,
                                   const float* __restrict__ b1,
                                   const float* __restrict__ w2,
                                   const float* __restrict__ b2) {
    __shared__ float h1[NH];
    int row = blockIdx.x;
    int j = threadIdx.x;
    float x = (float)row * (1.0f / (float)NBINS);
    h1[j] = elu_f(fmaf(w1[j], x, b1[j]));
    __syncthreads();
    float z = b2[j];
#pragma unroll 8
    for (int k = 0; k < NH; k++)
        z = fmaf(h1[k], w2[k * NH + j], z);
    g_table[row * NH + j] = elu_f(z);
}

// ---------------------------------------------------------------------------
// Kernel 2: one warp per person; fp32 NN table; packed f32x2 accumulation.
// ---------------------------------------------------------------------------
struct SM {
    float          table[TROWS_ALL * NH];  // 131584 B (row 513 = zeros)
    float          w3[NH * NH];            // 16384 B
    float          w4[NH * NH];            // 16384 B
    float          ifeat[NI];              // 1024 B
    unsigned short cmp[32][NI];            // 16384 B (compacted row offsets, float units)
    float          buf[32][NH];            // 8192 B  (per-warp h/u broadcast)
};                                         // ~190 KB

__global__ __launch_bounds__(1024, 1)
void vibo_main_kernel(const float* __restrict__ response,
                      const int*   __restrict__ mask,
                      const int*   __restrict__ item_index,
                      const float* __restrict__ eps_ability,
                      const float* __restrict__ eps_item,
                      const float* __restrict__ w3,
                      const float* __restrict__ b3,
                      const float* __restrict__ w4,
                      const float* __restrict__ b4,
                      const float* __restrict__ mu_table,
                      const float* __restrict__ logvar_table,
                      float* __restrict__ out) {
    extern __shared__ char smraw[];
    SM* s = (SM*)smraw;
    const int tid = threadIdx.x;
    const int nthr = blockDim.x;

    // ---- stage table (uint4) + weights + item features ----
    {
        const uint4* src = (const uint4*)g_table;
        uint4* dst = (uint4*)s->table;
        const int nv = (TROWS * NH) / 4;   // 8208
#pragma unroll 4
        for (int i = tid; i < nv; i += nthr) dst[i] = src[i];
        if (tid < 16) {                    // zero pad row 513
            uint4 z4 = make_uint4(0, 0, 0, 0);
            dst[(PADROW * NH) / 4 + tid] = z4;
        }
        const uint4* s3 = (const uint4*)w3;
        const uint4* s4 = (const uint4*)w4;
        uint4* d3 = (uint4*)s->w3;
        uint4* d4 = (uint4*)s->w4;
#pragma unroll 2
        for (int i = tid; i < (NH * NH) / 4; i += nthr) {
            d3[i] = s3[i];
            d4[i] = s4[i];
        }
    }
    if (tid < NI) {
        int idx = item_index[tid];
        float imu = mu_table[idx];
        float ilv = logvar_table[idx];
        s->ifeat[tid] = fmaf(eps_item[tid], __expf(0.5f * ilv), imu);
        if (blockIdx.x == 0) {
            out[O_IMU + tid] = imu;
            out[O_ILV + tid] = ilv;
        }
    }
    __syncthreads();

    const int wid  = tid >> 5;
    const int lane = tid & 31;
    const int wpc  = nthr >> 5;
    const int p = blockIdx.x * wpc + wid;
    if (p >= NP) return;

    // ---- load + compact masked items (8 per lane) ----
    const float4* rp = (const float4*)(response + p * NI);
    const int4*   mp = (const int4*)(mask + p * NI);
    float4 r0 = rp[lane * 2], r1 = rp[lane * 2 + 1];
    int4   m0 = mp[lane * 2], m1 = mp[lane * 2 + 1];
    float rv[8] = {r0.x, r0.y, r0.z, r0.w, r1.x, r1.y, r1.z, r1.w};
    int   mv[8] = {m0.x, m0.y, m0.z, m0.w, m1.x, m1.y, m1.z, m1.w};

    int cnt = 0;
#pragma unroll
    for (int j = 0; j < 8; j++) cnt += (mv[j] != 0);

    int off = cnt;
#pragma unroll
    for (int d = 1; d < 32; d <<= 1) {
        int t = __shfl_up_sync(0xffffffffu, off, d);
        if (lane >= d) off += t;
    }
    int total = __shfl_sync(0xffffffffu, off, 31);
    off -= cnt;

    unsigned short* cmp = s->cmp[wid];
    int pos = off;
#pragma unroll
    for (int j = 0; j < 8; j++) {
        if (mv[j]) {
            int b = __float2int_rn(rv[j] * (float)NBINS);
            if (b < 0) b = 0;
            if (b > NBINS) b = NBINS;
            cmp[pos++] = (unsigned short)(b << 6);   // float offset of row
        }
    }
    // pad to multiple of 4 with the zero row
    int totalp = (total + 3) & ~3;
    if (lane == 0) {
        for (int t = total; t < totalp; t++)
            cmp[t] = (unsigned short)(PADROW << 6);
    }
    __syncwarp();

    // ---- NN accumulate: per item = LDS.64 + add.rn.f32x2 ----
    const int d0 = lane * 2;
    const float* tabd = s->table + d0;
    const uint2* cw4 = (const uint2*)cmp;
    unsigned long long a0 = 0ull, a1 = 0ull;
    int n4 = totalp >> 2;
#pragma unroll 2
    for (int i = 0; i < n4; i++) {
        uint2 w = cw4[i];
        unsigned int o0 = w.x & 0xffffu, o1 = w.x >> 16;
        unsigned int o2 = w.y & 0xffffu, o3 = w.y >> 16;
        add2(a0, tabd + o0);
        add2(a1, tabd + o1);
        add2(a0, tabd + o2);
        add2(a1, tabd + o3);
    }
    asm("add.rn.f32x2 %0, %0, %1;" : "+l"(a0) : "l"(a1));
    float hx, hy;
    asm("mov.b64 {%0, %1}, %2;" : "=f"(hx), "=f"(hy) : "l"(a0));
    float inv = 1.0f / fmaxf((float)total, 1.0f);

    float* bufw = s->buf[wid];
    bufw[d0]     = hx * inv;
    bufw[d0 + 1] = hy * inv;
    __syncwarp();

    // ---- layer 3: u = elu(hm @ w3 + b3) ----
    float z0 = b3[d0], z1 = b3[d0 + 1];
    {
        const float4* hb = (const float4*)bufw;
#pragma unroll
        for (int k4 = 0; k4 < NH / 4; k4++) {
            float4 h = hb[k4];
            const float* wr = s->w3 + (k4 * 4) * NH + d0;
            float2 wa = *(const float2*)(wr);
            float2 wb = *(const float2*)(wr + NH);
            float2 wc = *(const float2*)(wr + 2 * NH);
            float2 wd = *(const float2*)(wr + 3 * NH);
            z0 = fmaf(h.x, wa.x, z0); z1 = fmaf(h.x, wa.y, z1);
            z0 = fmaf(h.y, wb.x, z0); z1 = fmaf(h.y, wb.y, z1);
            z0 = fmaf(h.z, wc.x, z0); z1 = fmaf(h.z, wc.y, z1);
            z0 = fmaf(h.w, wd.x, z0); z1 = fmaf(h.w, wd.y, z1);
        }
    }
    float u0 = elu_f(z0), u1 = elu_f(z1);
    __syncwarp();
    bufw[d0]     = u0;
    bufw[d0 + 1] = u1;
    __syncwarp();

    // ---- layer 4: o = u @ w4 + b4 ----
    float o0 = b4[d0], o1 = b4[d0 + 1];
    {
        const float4* hb = (const float4*)bufw;
#pragma unroll
        for (int k4 = 0; k4 < NH / 4; k4++) {
            float4 h = hb[k4];
            const float* wr = s->w4 + (k4 * 4) * NH + d0;
            float2 wa = *(const float2*)(wr);
            float2 wb = *(const float2*)(wr + NH);
            float2 wc = *(const float2*)(wr + 2 * NH);
            float2 wd = *(const float2*)(wr + 3 * NH);
            o0 = fmaf(h.x, wa.x, o0); o1 = fmaf(h.x, wa.y, o1);
            o0 = fmaf(h.y, wb.x, o0); o1 = fmaf(h.y, wb.y, o1);
            o0 = fmaf(h.z, wc.x, o0); o1 = fmaf(h.z, wc.y, o1);
            o0 = fmaf(h.w, wd.x, o0); o1 = fmaf(h.w, wd.y, o1);
        }
    }

    // ---- ability mu/logvar out ----
    float2 ov = make_float2(o0, o1);
    if (lane < 16) *(float2*)&out[O_AMU + p * NA + d0] = ov;
    else           *(float2*)&out[O_ALV + p * NA + (d0 - NA)] = ov;

    // ---- asum ----
    float lv0 = __shfl_down_sync(0xffffffffu, o0, 16);
    float lv1 = __shfl_down_sync(0xffffffffu, o1, 16);
    float term = 0.0f;
    if (lane < 16) {
        float2 eps = *(const float2*)&eps_ability[p * NA + d0];
        term = o0 + eps.x * __expf(0.5f * lv0)
             + o1 + eps.y * __expf(0.5f * lv1);
    }
#pragma unroll
    for (int w = 16; w > 0; w >>= 1)
        term += __shfl_xor_sync(0xffffffffu, term, w);
    float asum = term;

    // ---- response_mu = sigmoid(asum + ifeat), float4 I/O ----
    {
        const float4* ifp = (const float4*)(s->ifeat + lane * 8);
        float4* orow = (float4*)(out + p * NI + lane * 8);
#pragma unroll
        for (int v = 0; v < 2; v++) {
            float4 f = ifp[v];
            float4 r;
            r.x = __fdividef(1.0f, 1.0f + __expf(-(asum + f.x)));
            r.y = __fdividef(1.0f, 1.0f + __expf(-(asum + f.y)));
            r.z = __fdividef(1.0f, 1.0f + __expf(-(asum + f.z)));
            r.w = __fdividef(1.0f, 1.0f + __expf(-(asum + f.w)));
            orow[v] = r;
        }
    }
}

// ---------------------------------------------------------------------------
extern "C" void kernel_launch(void* const* d_in, const int* in_sizes, int n_in,
                              void* d_out, int out_size) {
    const float* response     = (const float*)d_in[0];
    const int*   mask         = (const int*)  d_in[1];
    const int*   item_index   = (const int*)  d_in[2];
    const float* eps_ability  = (const float*)d_in[3];
    const float* eps_item     = (const float*)d_in[4];
    const float* w1           = (const float*)d_in[5];
    const float* b1           = (const float*)d_in[6];
    const float* w2           = (const float*)d_in[7];
    const float* b2           = (const float*)d_in[8];
    const float* w3           = (const float*)d_in[9];
    const float* b3           = (const float*)d_in[10];
    const float* w4           = (const float*)d_in[11];
    const float* b4           = (const float*)d_in[12];
    const float* mu_table     = (const float*)d_in[13];
    const float* logvar_table = (const float*)d_in[14];
    float* out = (float*)d_out;

    cudaFuncSetAttribute(vibo_main_kernel,
                         cudaFuncAttributeMaxDynamicSharedMemorySize,
                         (int)sizeof(SM));

    build_table_kernel<<<TROWS, NH>>>(w1, b1, w2, b2);

    int sms = 148;
    cudaDeviceGetAttribute(&sms, cudaDevAttrMultiProcessorCount, 0);
    int wpc = (NP + sms - 1) / sms;
    if (wpc > 32) wpc = 32;
    if (wpc < 1)  wpc = 1;
    int grid = (NP + wpc - 1) / wpc;
    vibo_main_kernel<<<grid, wpc * 32, sizeof(SM)>>>(response, mask, item_index,
                                                     eps_ability, eps_item,
                                                     w3, b3, w4, b4,
                                                     mu_table, logvar_table, out);
}

// round 5
// speedup vs baseline: 4.4653x; 1.1083x over previous
#include <cuda_runtime.h>
#include <math.h>

#define NP 4096
#define NI 256
#define NH 64
#define NA 32

#define NBINS 512
#define TROWS (NBINS + 1)       // rows 0..512
#define PADOFF (TROWS * 128)    // byte offset of zero row 513
#define TROWS_ALL (TROWS + 1)

// Output layout (flattened tuple, fp32):
// response_mu [P*I] | ability_mu [P*A] | ability_logvar [P*A] | item_mu [I] | item_logvar [I]
#define O_AMU  (NP * NI)
#define O_ALV  (O_AMU + NP * NA)
#define O_IMU  (O_ALV + NP * NA)
#define O_ILV  (O_IMU + NI)

// bf16x2-packed h2 table: word w of row r packs dims (2w, 2w+1)
__device__ unsigned int g_table[TROWS * 32];

__device__ __forceinline__ float elu_ref(float x) {
    return x > 0.0f ? x : expm1f(x);
}
__device__ __forceinline__ float elu_fast(float x) {
    return x > 0.0f ? x : (__expf(x) - 1.0f);
}

// unpack bf16x2 word -> packed f32x2 add into acc (exact: bf16 = fp32 hi bits)
__device__ __forceinline__ void addbf2(unsigned long long& acc, unsigned int w) {
    asm("{\n\t"
        ".reg .b32 lo, hi;\n\t"
        ".reg .b64 t;\n\t"
        "shl.b32 lo, %1, 16;\n\t"
        "and.b32 hi, %1, 0xffff0000;\n\t"
        "mov.b64 t, {lo, hi};\n\t"
        "add.rn.f32x2 %0, %0, t;\n\t"
        "}" : "+l"(acc) : "r"(w));
}

// ---------------------------------------------------------------------------
// Kernel 1: build bf16x2 h2(x) table. One 64-thread block per bin row.
// ---------------------------------------------------------------------------
__global__ void build_table_kernel(const float* __restrict__ w1,
                                   const float* __restrict__ b1,
                                   const float* __restrict__ w2,
                                   const float* __restrict__ b2) {
    __shared__ float h1[NH];
    int row = blockIdx.x;
    int j = threadIdx.x;
    float x = (float)row * (1.0f / (float)NBINS);
    h1[j] = elu_ref(fmaf(w1[j], x, b1[j]));
    __syncthreads();
    float z = b2[j];
#pragma unroll 8
    for (int k = 0; k < NH; k++)
        z = fmaf(h1[k], w2[k * NH + j], z);
    z = elu_ref(z);
    float zo = __shfl_xor_sync(0xffffffffu, z, 1);  // partner (odd dim) value
    if ((j & 1) == 0) {
        unsigned int u;
        asm("cvt.rn.bf16x2.f32 %0, %1, %2;" : "=r"(u) : "f"(zo), "f"(z));
        g_table[row * 32 + (j >> 1)] = u;
    }
}

// ---------------------------------------------------------------------------
// Kernel 2: one warp per person; bf16x2 NN table (1 wf/item); u32 offsets.
// ---------------------------------------------------------------------------
struct SM {
    unsigned int table[TROWS_ALL * 32];  // 65792 B (row 513 = zeros)
    float        w3[NH * NH];            // 16384 B
    float        w4[NH * NH];            // 16384 B
    float        ifeat[NI];              // 1024 B
    unsigned int cmp[32][NI];            // 32768 B (compacted byte offsets)
    float        buf[32][NH];            // 8192 B
};                                       // ~140 KB

__global__ __launch_bounds__(896, 1)
void vibo_main_kernel(const float* __restrict__ response,
                      const int*   __restrict__ mask,
                      const int*   __restrict__ item_index,
                      const float* __restrict__ eps_ability,
                      const float* __restrict__ eps_item,
                      const float* __restrict__ w3,
                      const float* __restrict__ b3,
                      const float* __restrict__ w4,
                      const float* __restrict__ b4,
                      const float* __restrict__ mu_table,
                      const float* __restrict__ logvar_table,
                      float* __restrict__ out) {
    extern __shared__ char smraw[];
    SM* s = (SM*)smraw;
    const int tid = threadIdx.x;
    const int nthr = blockDim.x;
    const int wid  = tid >> 5;
    const int lane = tid & 31;
    const int wpc  = nthr >> 5;
    const int p = blockIdx.x * wpc + wid;

    // ---- issue this person's gmem loads early (overlap with staging) ----
    float4 r0, r1; int4 m0, m1;
    if (p < NP) {
        const float4* rp = (const float4*)(response + p * NI);
        const int4*   mp = (const int4*)(mask + p * NI);
        r0 = rp[lane * 2]; r1 = rp[lane * 2 + 1];
        m0 = mp[lane * 2]; m1 = mp[lane * 2 + 1];
    }

    // ---- stage table + weights ----
    {
        const uint4* src = (const uint4*)g_table;
        uint4* dst = (uint4*)s->table;
        const int nv = (TROWS * 32) / 4;   // 4104
#pragma unroll 4
        for (int i = tid; i < nv; i += nthr) dst[i] = src[i];
        if (tid < 8) dst[nv + tid] = make_uint4(0, 0, 0, 0);  // zero row 513
        const uint4* s3 = (const uint4*)w3;
        const uint4* s4 = (const uint4*)w4;
        uint4* d3 = (uint4*)s->w3;
        uint4* d4 = (uint4*)s->w4;
#pragma unroll 2
        for (int i = tid; i < (NH * NH) / 4; i += nthr) {
            d3[i] = s3[i];
            d4[i] = s4[i];
        }
    }
    if (tid < NI) {
        int idx = item_index[tid];
        float imu = mu_table[idx];
        float ilv = logvar_table[idx];
        s->ifeat[tid] = fmaf(eps_item[tid], __expf(0.5f * ilv), imu);
        if (blockIdx.x == 0) {
            out[O_IMU + tid] = imu;
            out[O_ILV + tid] = ilv;
        }
    }

    // ---- compaction (pre-sync: cmp region independent of staging) ----
    int total = 0;
    if (p < NP) {
        float rv[8] = {r0.x, r0.y, r0.z, r0.w, r1.x, r1.y, r1.z, r1.w};
        int   mv[8] = {m0.x, m0.y, m0.z, m0.w, m1.x, m1.y, m1.z, m1.w};
        int cnt = 0;
#pragma unroll
        for (int j = 0; j < 8; j++) cnt += (mv[j] != 0);
        int off = cnt;
#pragma unroll
        for (int d = 1; d < 32; d <<= 1) {
            int t = __shfl_up_sync(0xffffffffu, off, d);
            if (lane >= d) off += t;
        }
        total = __shfl_sync(0xffffffffu, off, 31);
        off -= cnt;
        unsigned int* cmp = s->cmp[wid];
        int pos = off;
#pragma unroll
        for (int j = 0; j < 8; j++) {
            if (mv[j]) {
                int b = __float2int_rn(rv[j] * (float)NBINS);
                if (b < 0) b = 0;
                if (b > NBINS) b = NBINS;
                cmp[pos++] = (unsigned int)(b << 7);   // byte offset of row
            }
        }
        int totalp = (total + 3) & ~3;
        if (lane == 0)
            for (int t = total; t < totalp; t++) cmp[t] = PADOFF;
    }
    __syncthreads();
    if (p >= NP) return;

    // ---- NN accumulate: per item = 1 LDS.32 + exact bf16 unpack + add2 ----
    const char* tb = (const char*)s->table + lane * 4;
    const uint4* cw4 = (const uint4*)s->cmp[wid];
    unsigned long long a0 = 0ull, a1 = 0ull;
    const int n4 = ((total + 3) & ~3) >> 2;
#pragma unroll 2
    for (int i = 0; i < n4; i++) {
        uint4 o = cw4[i];                          // broadcast LDS.128: 4 offsets
        unsigned int v0 = *(const unsigned int*)(tb + o.x);
        unsigned int v1 = *(const unsigned int*)(tb + o.y);
        unsigned int v2 = *(const unsigned int*)(tb + o.z);
        unsigned int v3 = *(const unsigned int*)(tb + o.w);
        addbf2(a0, v0);
        addbf2(a1, v1);
        addbf2(a0, v2);
        addbf2(a1, v3);
    }
    asm("add.rn.f32x2 %0, %0, %1;" : "+l"(a0) : "l"(a1));
    float hx, hy;
    asm("mov.b64 {%0, %1}, %2;" : "=f"(hx), "=f"(hy) : "l"(a0));
    float inv = 1.0f / fmaxf((float)total, 1.0f);

    const int d0 = lane * 2;
    float* bufw = s->buf[wid];
    bufw[d0]     = hx * inv;
    bufw[d0 + 1] = hy * inv;
    __syncwarp();

    // ---- layer 3: u = elu(hm @ w3 + b3) ----
    float z0 = b3[d0], z1 = b3[d0 + 1];
    {
        const float4* hb = (const float4*)bufw;
#pragma unroll
        for (int k4 = 0; k4 < NH / 4; k4++) {
            float4 h = hb[k4];
            const float* wr = s->w3 + (k4 * 4) * NH + d0;
            float2 wa = *(const float2*)(wr);
            float2 wb = *(const float2*)(wr + NH);
            float2 wc = *(const float2*)(wr + 2 * NH);
            float2 wd = *(const float2*)(wr + 3 * NH);
            z0 = fmaf(h.x, wa.x, z0); z1 = fmaf(h.x, wa.y, z1);
            z0 = fmaf(h.y, wb.x, z0); z1 = fmaf(h.y, wb.y, z1);
            z0 = fmaf(h.z, wc.x, z0); z1 = fmaf(h.z, wc.y, z1);
            z0 = fmaf(h.w, wd.x, z0); z1 = fmaf(h.w, wd.y, z1);
        }
    }
    float u0 = elu_fast(z0), u1 = elu_fast(z1);
    __syncwarp();
    bufw[d0]     = u0;
    bufw[d0 + 1] = u1;
    __syncwarp();

    // ---- layer 4: o = u @ w4 + b4 ----
    float o0 = b4[d0], o1 = b4[d0 + 1];
    {
        const float4* hb = (const float4*)bufw;
#pragma unroll
        for (int k4 = 0; k4 < NH / 4; k4++) {
            float4 h = hb[k4];
            const float* wr = s->w4 + (k4 * 4) * NH + d0;
            float2 wa = *(const float2*)(wr);
            float2 wb = *(const float2*)(wr + NH);
            float2 wc = *(const float2*)(wr + 2 * NH);
            float2 wd = *(const float2*)(wr + 3 * NH);
            o0 = fmaf(h.x, wa.x, o0); o1 = fmaf(h.x, wa.y, o1);
            o0 = fmaf(h.y, wb.x, o0); o1 = fmaf(h.y, wb.y, o1);
            o0 = fmaf(h.z, wc.x, o0); o1 = fmaf(h.z, wc.y, o1);
            o0 = fmaf(h.w, wd.x, o0); o1 = fmaf(h.w, wd.y, o1);
        }
    }

    // ---- ability mu/logvar out ----
    float2 ov = make_float2(o0, o1);
    if (lane < 16) *(float2*)&out[O_AMU + p * NA + d0] = ov;
    else           *(float2*)&out[O_ALV + p * NA + (d0 - NA)] = ov;

    // ---- asum ----
    float lv0 = __shfl_down_sync(0xffffffffu, o0, 16);
    float lv1 = __shfl_down_sync(0xffffffffu, o1, 16);
    float term = 0.0f;
    if (lane < 16) {
        float2 eps = *(const float2*)&eps_ability[p * NA + d0];
        term = o0 + eps.x * __expf(0.5f * lv0)
             + o1 + eps.y * __expf(0.5f * lv1);
    }
#pragma unroll
    for (int w = 16; w > 0; w >>= 1)
        term += __shfl_xor_sync(0xffffffffu, term, w);
    float asum = term;

    // ---- response_mu = sigmoid(asum + ifeat), float4 I/O ----
    {
        const float4* ifp = (const float4*)(s->ifeat + lane * 8);
        float4* orow = (float4*)(out + p * NI + lane * 8);
#pragma unroll
        for (int v = 0; v < 2; v++) {
            float4 f = ifp[v];
            float4 r;
            r.x = __fdividef(1.0f, 1.0f + __expf(-(asum + f.x)));
            r.y = __fdividef(1.0f, 1.0f + __expf(-(asum + f.y)));
            r.z = __fdividef(1.0f, 1.0f + __expf(-(asum + f.z)));
            r.w = __fdividef(1.0f, 1.0f + __expf(-(asum + f.w)));
            orow[v] = r;
        }
    }
}

// ---------------------------------------------------------------------------
extern "C" void kernel_launch(void* const* d_in, const int* in_sizes, int n_in,
                              void* d_out, int out_size) {
    const float* response     = (const float*)d_in[0];
    const int*   mask         = (const int*)  d_in[1];
    const int*   item_index   = (const int*)  d_in[2];
    const float* eps_ability  = (const float*)d_in[3];
    const float* eps_item     = (const float*)d_in[4];
    const float* w1           = (const float*)d_in[5];
    const float* b1           = (const float*)d_in[6];
    const float* w2           = (const float*)d_in[7];
    const float* b2           = (const float*)d_in[8];
    const float* w3           = (const float*)d_in[9];
    const float* b3           = (const float*)d_in[10];
    const float* w4           = (const float*)d_in[11];
    const float* b4           = (const float*)d_in[12];
    const float* mu_table     = (const float*)d_in[13];
    const float* logvar_table = (const float*)d_in[14];
    float* out = (float*)d_out;

    cudaFuncSetAttribute(vibo_main_kernel,
                         cudaFuncAttributeMaxDynamicSharedMemorySize,
                         (int)sizeof(SM));

    build_table_kernel<<<TROWS, NH>>>(w1, b1, w2, b2);

    int sms = 148;
    cudaDeviceGetAttribute(&sms, cudaDevAttrMultiProcessorCount, 0);
    int wpc = (NP + sms - 1) / sms;
    if (wpc > 28) wpc = 28;
    if (wpc < 1)  wpc = 1;
    int grid = (NP + wpc - 1) / wpc;
    vibo_main_kernel<<<grid, wpc * 32, sizeof(SM)>>>(response, mask, item_index,
                                                     eps_ability, eps_item,
                                                     w3, b3, w4, b4,
                                                     mu_table, logvar_table, out);
}